// round 11
// baseline (speedup 1.0000x reference)
#include <cuda_runtime.h>
#include <math.h>

#define BB 64
#define TT 256
#define FF 512
#define UU 1024
#define NB 128   // persistent CTAs (1/SM, all co-resident)

// dynamic smem: 131072 bytes (max tile: 64x128 A + 128x192 W floats)
#define SMEM_BYTES 131072

// ---------------------------------------------------------------------------
// Device-global scratch (no allocations allowed anywhere)
// ---------------------------------------------------------------------------
__device__ float g_XP[BB * TT * UU];        // x @ kernel_x precomputed
__device__ float g_zero[BB * UU];           // never written -> stays zero
__device__ float g_xx[BB * UU];
__device__ float g_c[BB * UU];              // LN2(longterm) carry
__device__ float g_st1[BB * UU];            // LN1(shortterm)
__device__ float g_att[BB * UU];
__device__ float g_xxp[16][BB * UU];        // split-K partials
__device__ float g_fip[8][BB * 2048];
__device__ float g_qkvp[8][BB * 3072];
__device__ float g_outp[16][BB * UU];
__device__ float g_Wfi[UU * 2048];          // [W_f | W_i]
__device__ float g_Wqkv[UU * 3072];         // [W_q | W_k | W_v]

// hierarchical grid-barrier state (cumulative across launches)
__device__ unsigned g_grp[8 * 64];          // 8 group counters, 256B apart
__device__ unsigned g_master;
__device__ volatile unsigned g_release;

__device__ __forceinline__ void gsync(unsigned &phase)
{
    __syncthreads();
    phase += 1u;
    if (threadIdx.x == 0) {
        __threadfence();
        unsigned p = atomicAdd(&g_grp[(blockIdx.x & 7) * 64], 1u);
        if (p == phase * 16u - 1u) {                 // last of my 16-CTA group
            unsigned m = atomicAdd(&g_master, 1u);
            if (m == phase * 8u - 1u) {              // last group overall
                __threadfence();
                g_release = phase;
            }
        }
        while (g_release < phase) { }
        __threadfence();
    }
    __syncthreads();
}

// ---------------------------------------------------------------------------
// 64-row x NCOL-col tile GEMM, K processed in KCH-deep single-fill chunks.
// 256 threads, 8x(NCOL/32) microtile. A smem row-major (broadcast reads),
// W smem row-major (contiguous conflict-free reads). fp32x2 packed FMA.
// ---------------------------------------------------------------------------
#define FMA2(acc, s, w) asm("fma.rn.f32x2 %0,%1,%2,%0;" : "+l"(acc) : "l"(s), "l"(w))
#define DUP(d, f)       asm("mov.b64 %0,{%1,%1};" : "=l"(d) : "f"(f))
#define UNPK(lo, hi, v) asm("mov.b64 {%0,%1},%2;" : "=f"(lo), "=f"(hi) : "l"(v))

template<int NCOL, int KCH>
__device__ void gemm_tile(
    const float* __restrict__ A, int lda,
    const float* __restrict__ W, int ldw,
    float* __restrict__ C, int ldc,
    int colbase, int k0, int ksz)
{
    extern __shared__ float dsm[];
    float* sA = dsm;                 // [64][KCH]
    float* sW = dsm + 64 * KCH;      // [KCH][NCOL]
    const int tid = threadIdx.x;
    const int tx = tid & 31;
    const int ty = tid >> 5;
    constexpr int NU = NCOL / 64;    // 64-bit accs per row: 128->2, 192->3

    unsigned long long acc[8][NU];
#pragma unroll
    for (int r = 0; r < 8; r++)
#pragma unroll
        for (int u = 0; u < NU; u++) acc[r][u] = 0ull;

    for (int kt = 0; kt < ksz; kt += KCH) {
        const int kg = k0 + kt;
        __syncthreads();
        // A fill: 64 rows x KCH, row-major, coalesced LDG.128 / STS.128
#pragma unroll
        for (int i = 0; i < 64 * KCH / 1024; i++) {
            int idx = tid + i * 256;
            int r = idx / (KCH / 4), k4 = (idx % (KCH / 4)) * 4;
            *(float4*)(sA + r * KCH + k4) =
                *(const float4*)(A + (size_t)r * lda + kg + k4);
        }
        // W fill: KCH rows x NCOL, coalesced
#pragma unroll
        for (int i = 0; i < KCH * NCOL / 1024; i++) {
            int idx = tid + i * 256;
            int kk = idx / (NCOL / 4), c4 = (idx % (NCOL / 4)) * 4;
            *(float4*)(sW + kk * NCOL + c4) =
                *(const float4*)(W + (size_t)(kg + kk) * ldw + colbase + c4);
        }
        __syncthreads();

#pragma unroll 2
        for (int k4 = 0; k4 < KCH / 4; k4++) {
            float4 a[8];
#pragma unroll
            for (int r = 0; r < 8; r++)
                a[r] = *(const float4*)(sA + (ty * 8 + r) * KCH + k4 * 4);
#pragma unroll
            for (int j = 0; j < 4; j++) {
                const float* wr = sW + (k4 * 4 + j) * NCOL;
                ulonglong2 w0 = *(const ulonglong2*)(wr + tx * 4);
                unsigned long long w2 = 0ull;
                if (NCOL == 192) w2 = *(const unsigned long long*)(wr + 128 + tx * 2);
#pragma unroll
                for (int r = 0; r < 8; r++) {
                    float av = (&a[r].x)[j];
                    unsigned long long s; DUP(s, av);
                    FMA2(acc[r][0], s, w0.x);
                    FMA2(acc[r][1], s, w0.y);
                    if (NCOL == 192) FMA2(acc[r][2], s, w2);
                }
            }
        }
    }

#pragma unroll
    for (int r = 0; r < 8; r++) {
        size_t base = (size_t)(ty * 8 + r) * ldc + colbase;
        float f0, f1, f2, f3;
        UNPK(f0, f1, acc[r][0]); UNPK(f2, f3, acc[r][1]);
        *(float4*)(C + base + tx * 4) = make_float4(f0, f1, f2, f3);
        if (NCOL == 192) {
            float f4, f5; UNPK(f4, f5, acc[r][2]);
            *(float2*)(C + base + 128 + tx * 2) = make_float2(f4, f5);
        }
    }
}

// ---------------------------------------------------------------------------
// Fused epilogue: reduce 8 f/i partials, gates, longterm, swish chain, both
// LayerNorms. One CTA per batch row b.
// ---------------------------------------------------------------------------
__device__ __noinline__ void fi_epi(int b,
    const float* __restrict__ g1, const float* __restrict__ b1,
    const float* __restrict__ g2, const float* __restrict__ b2)
{
    __shared__ float red[4][8];
    const int t = threadIdx.x;
    float st[4], lt[4];
    float s1 = 0.f, s2 = 0.f, s3 = 0.f, s4 = 0.f;

#pragma unroll
    for (int i = 0; i < 4; i++) {
        int j = t + i * 256;
        int base = b * 2048 + j;
        float fa = 0.f, ia = 0.f;
#pragma unroll
        for (int sp = 0; sp < 8; sp++) {
            fa += g_fip[sp][base];
            ia += g_fip[sp][base + 1024];
        }
        float xxv = g_xx[b * UU + j];
        float f    = 1.0f / (1.0f + expf(-fa));
        float ii   = 1.0f / (1.0f + expf(-ia));
        float cand = tanhf(xxv);
        float ltv  = f * g_c[b * UU + j] + ii * cand;
        float sxx  = xxv / (1.0f + expf(-xxv));            // swish(xx)
        float z    = ltv + sxx;
        float stv  = z / (1.0f + expf(-z));                // swish(lt + swish(xx))
        st[i] = stv; lt[i] = ltv;
        s1 += stv; s2 += stv * stv; s3 += ltv; s4 += ltv * ltv;
    }

    const int lane = t & 31, wid = t >> 5;
#pragma unroll
    for (int o = 16; o > 0; o >>= 1) {
        s1 += __shfl_down_sync(0xffffffffu, s1, o);
        s2 += __shfl_down_sync(0xffffffffu, s2, o);
        s3 += __shfl_down_sync(0xffffffffu, s3, o);
        s4 += __shfl_down_sync(0xffffffffu, s4, o);
    }
    if (lane == 0) { red[0][wid] = s1; red[1][wid] = s2; red[2][wid] = s3; red[3][wid] = s4; }
    __syncthreads();
    float S1 = 0.f, S2 = 0.f, S3 = 0.f, S4 = 0.f;
#pragma unroll
    for (int w = 0; w < 8; w++) { S1 += red[0][w]; S2 += red[1][w]; S3 += red[2][w]; S4 += red[3][w]; }
    const float inv = 1.0f / (float)UU;
    float m1 = S1 * inv, v1 = S2 * inv - m1 * m1;
    float m2 = S3 * inv, v2 = S4 * inv - m2 * m2;
    float r1 = rsqrtf(v1 + 1e-3f);
    float r2 = rsqrtf(v2 + 1e-3f);

#pragma unroll
    for (int i = 0; i < 4; i++) {
        int j = t + i * 256;
        g_st1[b * UU + j] = (st[i] - m1) * r1 * g1[j] + b1[j];
        g_c[b * UU + j]   = (lt[i] - m2) * r2 * g2[j] + b2[j];
    }
}

// ---------------------------------------------------------------------------
// Mini 8-head attention. One CTA per batch row; reduces 8 qkv partials.
// Uses dynamic smem overlay.
// ---------------------------------------------------------------------------
__device__ __noinline__ void attn(int b)
{
    extern __shared__ float dsm[];
    float* q  = dsm;
    float* k  = dsm + 1024;
    float* v  = dsm + 2048;
    float* sc = dsm + 3072;
    const int t = threadIdx.x;

    for (int j = t; j < 3072; j += 256) {
        int base = b * 3072 + j;
        float s = 0.f;
#pragma unroll
        for (int sp = 0; sp < 8; sp++) s += g_qkvp[sp][base];
        if (j < 1024)       q[j] = s;
        else if (j < 2048)  k[j - 1024] = s;
        else                v[j - 2048] = s;
    }
    __syncthreads();

    if (t < 64) {
        int h = t >> 3, g = t & 7;
        float s = 0.f;
#pragma unroll 8
        for (int d = 0; d < 128; d++) s += q[h * 128 + d] * k[g * 128 + d];
        sc[t] = s * 0.08838834764831845f;   // 1/sqrt(128)
    }
    __syncthreads();

    if (t < 8) {
        float mx = -1e30f;
#pragma unroll
        for (int g = 0; g < 8; g++) mx = fmaxf(mx, sc[t * 8 + g]);
        float e[8], sum = 0.f;
#pragma unroll
        for (int g = 0; g < 8; g++) { e[g] = expf(sc[t * 8 + g] - mx); sum += e[g]; }
        float is = 1.0f / sum;
#pragma unroll
        for (int g = 0; g < 8; g++) sc[t * 8 + g] = e[g] * is;
    }
    __syncthreads();

    for (int j = t; j < 1024; j += 256) {
        int h = j >> 7, d = j & 127;
        float a = 0.f;
#pragma unroll
        for (int g = 0; g < 8; g++) a += sc[h * 8 + g] * v[g * 128 + d];
        g_att[b * UU + j] = a;
    }
}

// ---------------------------------------------------------------------------
// The single persistent kernel.
// ---------------------------------------------------------------------------
__global__ void __launch_bounds__(256, 1) persist(
    const float* __restrict__ x,  const float* __restrict__ kx, const float* __restrict__ kh,
    const float* __restrict__ Wq, const float* __restrict__ Wk, const float* __restrict__ Wv,
    const float* __restrict__ Wo, const float* __restrict__ Wf, const float* __restrict__ Wi,
    const float* __restrict__ g1, const float* __restrict__ b1,
    const float* __restrict__ g2, const float* __restrict__ b2,
    float* __restrict__ y)
{
    unsigned phase = g_release;                       // carries across launches
    const int tid = threadIdx.x;
    const int bid = blockIdx.x;
    const int gt  = bid * 256 + tid;                  // 0..32767

    // phase 0: pack fused weights, zero carry
    for (int i = gt; i < UU * 2048; i += NB * 256) {
        int kk = i >> 11, j = i & 2047;
        g_Wfi[i] = (j < 1024) ? Wf[(kk << 10) + j] : Wi[(kk << 10) + j - 1024];
    }
    for (int i = gt; i < UU * 3072; i += NB * 256) {
        int kk = i / 3072, j = i - kk * 3072;
        float vv = (j < 1024) ? Wq[kk * 1024 + j]
                 : (j < 2048) ? Wk[kk * 1024 + j - 1024]
                              : Wv[kk * 1024 + j - 2048];
        g_Wqkv[i] = vv;
    }
    for (int i = gt; i < BB * UU; i += NB * 256) g_c[i] = 0.f;
    gsync(phase);

    // XP = x @ kernel_x : 256 rowtiles x 8 coltiles(128), full K=512
    for (int u = bid; u < 2048; u += NB) {
        int rt = u >> 3, ct = u & 7;
        gemm_tile<128, 128>(x + (size_t)rt * 64 * FF, FF, kx, UU,
                            g_XP + (size_t)rt * 64 * UU, UU, ct * 128, 0, FF);
    }
    gsync(phase);

    for (int t = 0; t < TT; t++) {
        const float* h = (t == 0) ? g_zero : (y + (size_t)(t - 1) * UU);
        const int ldh  = (t == 0) ? UU : (TT * UU);

        // ph1: xx partials = h @ kernel_h  (8 ct x 16 sp, ksz 64)
        {
            int ks = bid >> 3, ct = bid & 7;
            gemm_tile<128, 64>(h, ldh, kh, UU, g_xxp[ks], UU, ct * 128, ks * 64, 64);
        }
        gsync(phase);

        // ph2: xx = XP[:,t,:] + sum of 16 partials
        for (int i = gt; i < BB * UU; i += NB * 256) {
            int b = i >> 10, uu = i & 1023;
            float s = g_XP[(size_t)((b << 8) + t) * UU + uu];
#pragma unroll
            for (int sp = 0; sp < 16; sp++) s += g_xxp[sp][i];
            g_xx[i] = s;
        }
        gsync(phase);

        // ph3: [f|i] partials = xx @ Wfi  (16 ct x 8 sp, ksz 128)
        {
            int ks = bid >> 4, ct = bid & 15;
            gemm_tile<128, 128>(g_xx, UU, g_Wfi, 2048, g_fip[ks], 2048,
                                ct * 128, ks * 128, 128);
        }
        gsync(phase);

        // ph4: gates + swish + both LayerNorms
        if (bid < 64) fi_epi(bid, g1, b1, g2, b2);
        gsync(phase);

        // ph5: [q|k|v] partials = st1 @ Wqkv  (16 ct(192) x 8 sp, ksz 128)
        {
            int ks = bid >> 4, ct = bid & 15;
            gemm_tile<192, 128>(g_st1, UU, g_Wqkv, 3072, g_qkvp[ks], 3072,
                                ct * 192, ks * 128, 128);
        }
        gsync(phase);

        // ph6: attention
        if (bid < 64) attn(bid);
        gsync(phase);

        // ph7: out partials = attended @ W_o  (8 ct x 16 sp, ksz 64)
        {
            int ks = bid >> 3, ct = bid & 7;
            gemm_tile<128, 64>(g_att, UU, Wo, UU, g_outp[ks], UU, ct * 128, ks * 64, 64);
        }
        gsync(phase);

        // ph8: y[:,t,:] = st1 + sum of 16 partials  (= h for t+1)
        for (int i = gt; i < BB * UU; i += NB * 256) {
            int b = i >> 10, uu = i & 1023;
            float s = g_st1[i];
#pragma unroll
            for (int sp = 0; sp < 16; sp++) s += g_outp[sp][i];
            y[(size_t)b * (TT * UU) + (size_t)t * UU + uu] = s;
        }
        gsync(phase);
    }
}

// ---------------------------------------------------------------------------
// Host: ONE launch -> one graph node.
// ---------------------------------------------------------------------------
extern "C" void kernel_launch(void* const* d_in, const int* in_sizes, int n_in,
                              void* d_out, int out_size)
{
    (void)in_sizes; (void)n_in; (void)out_size;
    cudaFuncSetAttribute(persist, cudaFuncAttributeMaxDynamicSharedMemorySize,
                         SMEM_BYTES);
    persist<<<NB, 256, SMEM_BYTES>>>(
        (const float*)d_in[0],  (const float*)d_in[1],  (const float*)d_in[2],
        (const float*)d_in[3],  (const float*)d_in[4],  (const float*)d_in[5],
        (const float*)d_in[6],  (const float*)d_in[7],  (const float*)d_in[8],
        (const float*)d_in[9],  (const float*)d_in[10],
        (const float*)d_in[11], (const float*)d_in[12],
        (float*)d_out);
}

// round 14
// speedup vs baseline: 1.5187x; 1.5187x over previous
#include <cuda_runtime.h>
#include <math.h>

#define BB 64
#define TT 256
#define FF 512
#define UU 1024
#define NB 128            // persistent CTAs, 1/SM, all co-resident
#define SMEM_BYTES 65536  // 2 x (64x32 A + 32x192 W) floats

// ---------------------------------------------------------------------------
// Device-global scratch (no allocations anywhere)
// ---------------------------------------------------------------------------
__device__ float g_XP[BB * TT * UU];        // x @ kernel_x precomputed
__device__ float g_zero[BB * UU];           // never written -> stays zero
__device__ float g_xx[BB * UU];
__device__ float g_c[BB * UU];              // LN2(longterm) carry
__device__ float g_st1[BB * UU];            // LN1(shortterm)
__device__ float g_att[BB * UU];
__device__ float g_xxp[16][BB * UU];        // split-K partials
__device__ float g_fip[8][BB * 2048];
__device__ float g_qkvp[8][BB * 3072];
__device__ float g_outp[16][BB * UU];
__device__ float g_Wfi[UU * 2048];          // [W_f | W_i]
__device__ float g_Wqkv[UU * 3072];         // [W_q | W_k | W_v]

// hierarchical grid-barrier state (cumulative across launches)
__device__ unsigned g_grp[8 * 64];          // 8 group counters, 256B apart
__device__ unsigned g_master;
__device__ volatile unsigned g_release;

__device__ __forceinline__ void gsync(unsigned &phase)
{
    __syncthreads();
    phase += 1u;
    if (threadIdx.x == 0) {
        __threadfence();
        unsigned p = atomicAdd(&g_grp[(blockIdx.x & 7) * 64], 1u);
        if (p == phase * 16u - 1u) {
            unsigned m = atomicAdd(&g_master, 1u);
            if (m == phase * 8u - 1u) {
                __threadfence();
                g_release = phase;
            }
        }
        while (g_release < phase) { }
        __threadfence();
    }
    __syncthreads();
}

// ---------------------------------------------------------------------------
// fp32x2 packed FMA + cp.async helpers
// ---------------------------------------------------------------------------
#define FMA2(acc, s, w) asm("fma.rn.f32x2 %0,%1,%2,%0;" : "+l"(acc) : "l"(s), "l"(w))
#define DUP(d, f)       asm("mov.b64 %0,{%1,%1};" : "=l"(d) : "f"(f))
#define UNPK(lo, hi, v) asm("mov.b64 {%0,%1},%2;" : "=f"(lo), "=f"(hi) : "l"(v))

__device__ __forceinline__ void cpa16(unsigned d, const void* s)
{
    asm volatile("cp.async.cg.shared.global [%0], [%1], 16;" :: "r"(d), "l"(s));
}
#define CP_COMMIT() asm volatile("cp.async.commit_group;")
#define CP_WAIT0()  asm volatile("cp.async.wait_group 0;")
#define CP_WAIT1()  asm volatile("cp.async.wait_group 1;")

// ---------------------------------------------------------------------------
// 64-row x NCOL-col tile GEMM, K in 32-deep double-buffered cp.async chunks.
// 256 threads: ty = tid>>5 (8 row-groups of 8 rows), tx = lane.
// NCOL=128: 8r x 4c per thread.  NCOL=192: 8r x 6c per thread.
// (Equivalence of this implementation with the validated synchronous one was
//  established experimentally: both produce identical outputs.)
// ---------------------------------------------------------------------------
template<int NCOL>
__device__ void gemm_tile(
    const float* __restrict__ A, int lda,
    const float* __restrict__ W, int ldw,
    float* __restrict__ C, int ldc,
    int colbase, int k0, int ksz)
{
    extern __shared__ float dsm[];
    constexpr int BUF = 2048 + 32 * NCOL;   // floats per buffer
    constexpr int NU  = NCOL / 64;          // 128->2, 192->3
    const int tid = threadIdx.x;
    const int tx = tid & 31;
    const int ty = tid >> 5;

    unsigned long long acc[8][NU];
#pragma unroll
    for (int r = 0; r < 8; r++)
#pragma unroll
        for (int u = 0; u < NU; u++) acc[r][u] = 0ull;

    auto fill = [&](int bf, int kg) {
        float* sA = dsm + bf * BUF;
        float* sW = sA + 2048;
        unsigned aA = (unsigned)__cvta_generic_to_shared(sA);
        unsigned aW = (unsigned)__cvta_generic_to_shared(sW);
#pragma unroll
        for (int i = 0; i < 2; i++) {
            int idx = tid + i * 256;                 // 0..511
            int r = idx >> 3, k4 = (idx & 7) << 2;
            cpa16(aA + (unsigned)(r * 32 + k4) * 4,
                  A + (size_t)r * lda + kg + k4);
        }
#pragma unroll
        for (int i = 0; i < (NCOL == 192 ? 6 : 4); i++) {
            int idx = tid + i * 256;
            int kk = idx / (NCOL / 4), c4 = (idx % (NCOL / 4)) * 4;
            cpa16(aW + (unsigned)(kk * NCOL + c4) * 4,
                  W + (size_t)(kg + kk) * ldw + colbase + c4);
        }
        CP_COMMIT();
    };

    fill(0, k0);
    const int nch = ksz >> 5;
    for (int c = 0; c < nch; c++) {
        if (c + 1 < nch) { fill((c + 1) & 1, k0 + ((c + 1) << 5)); CP_WAIT1(); }
        else             { CP_WAIT0(); }
        __syncthreads();
        const float* sA = dsm + (c & 1) * BUF;
        const float* sW = sA + 2048;
#pragma unroll
        for (int k4 = 0; k4 < 8; k4++) {
            float4 a[8];
#pragma unroll
            for (int r = 0; r < 8; r++)
                a[r] = *(const float4*)(sA + (ty * 8 + r) * 32 + k4 * 4);
#pragma unroll
            for (int j = 0; j < 4; j++) {
                const float* wr = sW + (k4 * 4 + j) * NCOL;
                ulonglong2 w0 = *(const ulonglong2*)(wr + tx * 4);
                unsigned long long w2 = 0ull;
                if (NCOL == 192)
                    w2 = *(const unsigned long long*)(wr + 128 + tx * 2);
#pragma unroll
                for (int r = 0; r < 8; r++) {
                    unsigned long long s; DUP(s, (&a[r].x)[j]);
                    FMA2(acc[r][0], s, w0.x);
                    FMA2(acc[r][1], s, w0.y);
                    if (NCOL == 192) FMA2(acc[r][2], s, w2);
                }
            }
        }
        __syncthreads();
    }

#pragma unroll
    for (int r = 0; r < 8; r++) {
        size_t base = (size_t)(ty * 8 + r) * ldc + colbase;
        float f0, f1, f2, f3;
        UNPK(f0, f1, acc[r][0]); UNPK(f2, f3, acc[r][1]);
        *(float4*)(C + base + tx * 4) = make_float4(f0, f1, f2, f3);
        if (NCOL == 192) {
            float f4, f5; UNPK(f4, f5, acc[r][2]);
            *(float2*)(C + base + 128 + tx * 2) = make_float2(f4, f5);
        }
    }
}

// ---------------------------------------------------------------------------
// ph4: reduce 8 f/i partials + gates + longterm + swish chain + both
// LayerNorms. One CTA per batch row b. (verbatim from the passing R11 kernel)
// ---------------------------------------------------------------------------
__device__ __noinline__ void fi_epi(int b,
    const float* __restrict__ g1, const float* __restrict__ b1,
    const float* __restrict__ g2, const float* __restrict__ b2)
{
    __shared__ float red[4][8];
    const int t = threadIdx.x;
    float st[4], lt[4];
    float s1 = 0.f, s2 = 0.f, s3 = 0.f, s4 = 0.f;

#pragma unroll
    for (int i = 0; i < 4; i++) {
        int j = t + i * 256;
        int base = b * 2048 + j;
        float fa = 0.f, ia = 0.f;
#pragma unroll
        for (int sp = 0; sp < 8; sp++) {
            fa += g_fip[sp][base];
            ia += g_fip[sp][base + 1024];
        }
        float xxv = g_xx[b * UU + j];
        float f    = 1.0f / (1.0f + expf(-fa));
        float ii   = 1.0f / (1.0f + expf(-ia));
        float cand = tanhf(xxv);
        float ltv  = f * g_c[b * UU + j] + ii * cand;
        float sxx  = xxv / (1.0f + expf(-xxv));            // swish(xx)
        float z    = ltv + sxx;
        float stv  = z / (1.0f + expf(-z));                // swish(lt + swish(xx))
        st[i] = stv; lt[i] = ltv;
        s1 += stv; s2 += stv * stv; s3 += ltv; s4 += ltv * ltv;
    }

    const int lane = t & 31, wid = t >> 5;
#pragma unroll
    for (int o = 16; o > 0; o >>= 1) {
        s1 += __shfl_down_sync(0xffffffffu, s1, o);
        s2 += __shfl_down_sync(0xffffffffu, s2, o);
        s3 += __shfl_down_sync(0xffffffffu, s3, o);
        s4 += __shfl_down_sync(0xffffffffu, s4, o);
    }
    if (lane == 0) { red[0][wid] = s1; red[1][wid] = s2; red[2][wid] = s3; red[3][wid] = s4; }
    __syncthreads();
    float S1 = 0.f, S2 = 0.f, S3 = 0.f, S4 = 0.f;
#pragma unroll
    for (int w = 0; w < 8; w++) { S1 += red[0][w]; S2 += red[1][w]; S3 += red[2][w]; S4 += red[3][w]; }
    const float inv = 1.0f / (float)UU;
    float m1 = S1 * inv, v1 = S2 * inv - m1 * m1;
    float m2 = S3 * inv, v2 = S4 * inv - m2 * m2;
    float r1 = rsqrtf(v1 + 1e-3f);
    float r2 = rsqrtf(v2 + 1e-3f);

#pragma unroll
    for (int i = 0; i < 4; i++) {
        int j = t + i * 256;
        g_st1[b * UU + j] = (st[i] - m1) * r1 * g1[j] + b1[j];
        g_c[b * UU + j]   = (lt[i] - m2) * r2 * g2[j] + b2[j];
    }
}

// ---------------------------------------------------------------------------
// ph6: mini 8-head attention, one CTA per batch row, 8 qkv partials.
// ---------------------------------------------------------------------------
__device__ __noinline__ void attn(int b)
{
    extern __shared__ float dsm[];
    float* q  = dsm;
    float* k  = dsm + 1024;
    float* v  = dsm + 2048;
    float* sc = dsm + 3072;
    const int t = threadIdx.x;

    for (int j = t; j < 3072; j += 256) {
        int base = b * 3072 + j;
        float s = 0.f;
#pragma unroll
        for (int sp = 0; sp < 8; sp++) s += g_qkvp[sp][base];
        if (j < 1024)       q[j] = s;
        else if (j < 2048)  k[j - 1024] = s;
        else                v[j - 2048] = s;
    }
    __syncthreads();

    if (t < 64) {
        int h = t >> 3, g = t & 7;
        float s = 0.f;
#pragma unroll 8
        for (int d = 0; d < 128; d++) s += q[h * 128 + d] * k[g * 128 + d];
        sc[t] = s * 0.08838834764831845f;   // 1/sqrt(128)
    }
    __syncthreads();

    if (t < 8) {
        float mx = -1e30f;
#pragma unroll
        for (int g = 0; g < 8; g++) mx = fmaxf(mx, sc[t * 8 + g]);
        float e[8], sum = 0.f;
#pragma unroll
        for (int g = 0; g < 8; g++) { e[g] = expf(sc[t * 8 + g] - mx); sum += e[g]; }
        float is = 1.0f / sum;
#pragma unroll
        for (int g = 0; g < 8; g++) sc[t * 8 + g] = e[g] * is;
    }
    __syncthreads();

    for (int j = t; j < 1024; j += 256) {
        int h = j >> 7, d = j & 127;
        float a = 0.f;
#pragma unroll
        for (int g = 0; g < 8; g++) a += sc[h * 8 + g] * v[g * 128 + d];
        g_att[b * UU + j] = a;
    }
}

// ---------------------------------------------------------------------------
// The single persistent kernel (phase structure verbatim from passing R11).
// ---------------------------------------------------------------------------
__global__ void __launch_bounds__(256, 1) persist(
    const float* __restrict__ x,  const float* __restrict__ kx, const float* __restrict__ kh,
    const float* __restrict__ Wq, const float* __restrict__ Wk, const float* __restrict__ Wv,
    const float* __restrict__ Wo, const float* __restrict__ Wf, const float* __restrict__ Wi,
    const float* __restrict__ g1, const float* __restrict__ b1,
    const float* __restrict__ g2, const float* __restrict__ b2,
    float* __restrict__ y)
{
    unsigned phase = g_release;                 // carries across launches
    const int tid = threadIdx.x;
    const int bid = blockIdx.x;
    const int gt  = bid * 256 + tid;

    // phase 0: pack fused weights, zero carry
    for (int i = gt; i < UU * 2048; i += NB * 256) {
        int kk = i >> 11, j = i & 2047;
        g_Wfi[i] = (j < 1024) ? Wf[(kk << 10) + j] : Wi[(kk << 10) + j - 1024];
    }
    for (int i = gt; i < UU * 3072; i += NB * 256) {
        int kk = i / 3072, j = i - kk * 3072;
        float vv = (j < 1024) ? Wq[kk * 1024 + j]
                 : (j < 2048) ? Wk[kk * 1024 + j - 1024]
                              : Wv[kk * 1024 + j - 2048];
        g_Wqkv[i] = vv;
    }
    for (int i = gt; i < BB * UU; i += NB * 256) g_c[i] = 0.f;
    gsync(phase);

    // XP = x @ kernel_x : 256 rowtiles x 8 coltiles(128), full K=512
    for (int u = bid; u < 2048; u += NB) {
        int rt = u >> 3, ct = u & 7;
        gemm_tile<128>(x + (size_t)rt * 64 * FF, FF, kx, UU,
                       g_XP + (size_t)rt * 64 * UU, UU, ct * 128, 0, FF);
    }
    gsync(phase);

    for (int t = 0; t < TT; t++) {
        const float* h = (t == 0) ? g_zero : (y + (size_t)(t - 1) * UU);
        const int ldh  = (t == 0) ? UU : (TT * UU);

        // ph1: xx partials = h @ kernel_h  (8 ct x 16 sp, ksz 64)
        {
            int ks = bid >> 3, ct = bid & 7;
            gemm_tile<128>(h, ldh, kh, UU, g_xxp[ks], UU, ct * 128, ks * 64, 64);
        }
        gsync(phase);

        // ph2: xx = XP[:,t,:] + sum of 16 partials
        for (int i = gt; i < BB * UU; i += NB * 256) {
            int b = i >> 10, uu = i & 1023;
            float s = g_XP[(size_t)((b << 8) + t) * UU + uu];
#pragma unroll
            for (int sp = 0; sp < 16; sp++) s += g_xxp[sp][i];
            g_xx[i] = s;
        }
        gsync(phase);

        // ph3: [f|i] partials = xx @ Wfi  (16 ct x 8 sp, ksz 128)
        {
            int ks = bid >> 4, ct = bid & 15;
            gemm_tile<128>(g_xx, UU, g_Wfi, 2048, g_fip[ks], 2048,
                           ct * 128, ks * 128, 128);
        }
        gsync(phase);

        // ph4: gates + swish + both LayerNorms
        if (bid < 64) fi_epi(bid, g1, b1, g2, b2);
        gsync(phase);

        // ph5: [q|k|v] partials = st1 @ Wqkv  (16 ct(192) x 8 sp, ksz 128)
        {
            int ks = bid >> 4, ct = bid & 15;
            gemm_tile<192>(g_st1, UU, g_Wqkv, 3072, g_qkvp[ks], 3072,
                           ct * 192, ks * 128, 128);
        }
        gsync(phase);

        // ph6: attention
        if (bid < 64) attn(bid);
        gsync(phase);

        // ph7: out partials = attended @ W_o  (8 ct x 16 sp, ksz 64)
        {
            int ks = bid >> 3, ct = bid & 7;
            gemm_tile<128>(g_att, UU, Wo, UU, g_outp[ks], UU,
                           ct * 128, ks * 64, 64);
        }
        gsync(phase);

        // ph8: y[:,t,:] = st1 + sum of 16 partials  (= h for t+1)
        for (int i = gt; i < BB * UU; i += NB * 256) {
            int b = i >> 10, uu = i & 1023;
            float s = g_st1[i];
#pragma unroll
            for (int sp = 0; sp < 16; sp++) s += g_outp[sp][i];
            y[(size_t)b * (TT * UU) + (size_t)t * UU + uu] = s;
        }
        gsync(phase);
    }
}

// ---------------------------------------------------------------------------
// Host: ONE launch -> one graph node.
// ---------------------------------------------------------------------------
extern "C" void kernel_launch(void* const* d_in, const int* in_sizes, int n_in,
                              void* d_out, int out_size)
{
    (void)in_sizes; (void)n_in; (void)out_size;
    cudaFuncSetAttribute(persist, cudaFuncAttributeMaxDynamicSharedMemorySize,
                         SMEM_BYTES);
    persist<<<NB, 256, SMEM_BYTES>>>(
        (const float*)d_in[0],  (const float*)d_in[1],  (const float*)d_in[2],
        (const float*)d_in[3],  (const float*)d_in[4],  (const float*)d_in[5],
        (const float*)d_in[6],  (const float*)d_in[7],  (const float*)d_in[8],
        (const float*)d_in[9],  (const float*)d_in[10],
        (const float*)d_in[11], (const float*)d_in[12],
        (float*)d_out);
}

// round 16
// speedup vs baseline: 1.5804x; 1.0406x over previous
#include <cuda_runtime.h>
#include <math.h>

#define BB 64
#define TT 256
#define FF 512
#define UU 1024
#define NB 128             // persistent CTAs, 1/SM, all co-resident
#define NT 512             // threads per CTA -> 16 warps/SM
// dynamic smem: 2 x (64x32 A + 32x384 W) floats = 2 x 14336 x 4B
#define SMEM_BYTES 114688

// ---------------------------------------------------------------------------
// Device-global scratch (no allocations anywhere)
// ---------------------------------------------------------------------------
__device__ float g_XP[BB * TT * UU];        // x @ kernel_x precomputed
__device__ float g_zero[BB * UU];           // never written -> stays zero
__device__ float g_xx[BB * UU];
__device__ float g_c[BB * UU];              // LN2(longterm) carry
__device__ float g_st1[BB * UU];            // LN1(shortterm)
__device__ float g_att[BB * UU];
__device__ float g_xxp[32][BB * UU];        // split-K partials
__device__ float g_fip[16][BB * 2048];
__device__ float g_qkvp[16][BB * 3072];
__device__ float g_outp[32][BB * UU];
__device__ float g_Wfi[UU * 2048];          // [W_f | W_i]
__device__ float g_Wqkv[UU * 3072];         // [W_q | W_k | W_v]

// hierarchical grid-barrier state (cumulative across launches)
__device__ unsigned g_grp[8 * 64];          // 8 group counters, 256B apart
__device__ unsigned g_master;
__device__ volatile unsigned g_release;

__device__ __forceinline__ void gsync(unsigned &phase)
{
    __syncthreads();
    phase += 1u;
    if (threadIdx.x == 0) {
        __threadfence();
        unsigned p = atomicAdd(&g_grp[(blockIdx.x & 7) * 64], 1u);
        if (p == phase * 16u - 1u) {
            unsigned m = atomicAdd(&g_master, 1u);
            if (m == phase * 8u - 1u) {
                __threadfence();
                g_release = phase;
            }
        }
        while (g_release < phase) { }
        __threadfence();
    }
    __syncthreads();
}

// ---------------------------------------------------------------------------
// fp32x2 packed FMA + cp.async helpers
// ---------------------------------------------------------------------------
#define FMA2(acc, s, w) asm("fma.rn.f32x2 %0,%1,%2,%0;" : "+l"(acc) : "l"(s), "l"(w))
#define DUP(d, f)       asm("mov.b64 %0,{%1,%1};" : "=l"(d) : "f"(f))
#define UNPK(lo, hi, v) asm("mov.b64 {%0,%1},%2;" : "=f"(lo), "=f"(hi) : "l"(v))

__device__ __forceinline__ void cpa16(unsigned d, const void* s)
{
    asm volatile("cp.async.cg.shared.global [%0], [%1], 16;" :: "r"(d), "l"(s));
}
#define CP_COMMIT() asm volatile("cp.async.commit_group;")
#define CP_WAIT0()  asm volatile("cp.async.wait_group 0;")
#define CP_WAIT1()  asm volatile("cp.async.wait_group 1;")

// ---------------------------------------------------------------------------
// 64-row x NCOL-col tile GEMM, K in 32-deep double-buffered cp.async chunks.
// 512 threads: ty = tid>>6 (8 row-groups of 8 rows), tx = tid&63.
// NCOL=256: 8r x 4c per thread (cols tx*4..+3).
// NCOL=384: 8r x 6c per thread (cols tx*4..+3 and 256+tx*2..+1).
// A-reads are warp-uniform (broadcast); W-reads contiguous, conflict-free.
// ---------------------------------------------------------------------------
template<int NCOL>
__device__ void gemm_tile(
    const float* __restrict__ A, int lda,
    const float* __restrict__ W, int ldw,
    float* __restrict__ C, int ldc,
    int colbase, int k0, int ksz)
{
    extern __shared__ float dsm[];
    constexpr int BUF = 2048 + 32 * NCOL;   // floats per buffer
    constexpr int NU  = NCOL / 128;         // 256->2, 384->3
    const int tid = threadIdx.x;
    const int tx = tid & 63;
    const int ty = tid >> 6;

    unsigned long long acc[8][NU];
#pragma unroll
    for (int r = 0; r < 8; r++)
#pragma unroll
        for (int u = 0; u < NU; u++) acc[r][u] = 0ull;

    auto fill = [&](int bf, int kg) {
        float* sA = dsm + bf * BUF;
        float* sW = sA + 2048;
        unsigned aA = (unsigned)__cvta_generic_to_shared(sA);
        unsigned aW = (unsigned)__cvta_generic_to_shared(sW);
        {   // A: 64 rows x 32 k, one float4 per thread
            int r = tid >> 3, k4 = (tid & 7) << 2;
            cpa16(aA + (unsigned)(r * 32 + k4) * 4,
                  A + (size_t)r * lda + kg + k4);
        }
#pragma unroll
        for (int i = 0; i < NCOL / 64; i++) {   // W: 32 x NCOL
            int idx = tid + i * NT;
            int kk = idx / (NCOL / 4), c4 = (idx % (NCOL / 4)) * 4;
            cpa16(aW + (unsigned)(kk * NCOL + c4) * 4,
                  W + (size_t)(kg + kk) * ldw + colbase + c4);
        }
        CP_COMMIT();
    };

    fill(0, k0);
    const int nch = ksz >> 5;
    for (int c = 0; c < nch; c++) {
        if (c + 1 < nch) { fill((c + 1) & 1, k0 + ((c + 1) << 5)); CP_WAIT1(); }
        else             { CP_WAIT0(); }
        __syncthreads();
        const float* sA = dsm + (c & 1) * BUF;
        const float* sW = sA + 2048;
#pragma unroll
        for (int k4 = 0; k4 < 8; k4++) {
            float4 a[8];
#pragma unroll
            for (int r = 0; r < 8; r++)
                a[r] = *(const float4*)(sA + (ty * 8 + r) * 32 + k4 * 4);
#pragma unroll
            for (int j = 0; j < 4; j++) {
                const float* wr = sW + (k4 * 4 + j) * NCOL;
                ulonglong2 w0 = *(const ulonglong2*)(wr + tx * 4);
                unsigned long long w2 = 0ull;
                if (NCOL == 384)
                    w2 = *(const unsigned long long*)(wr + 256 + tx * 2);
#pragma unroll
                for (int r = 0; r < 8; r++) {
                    unsigned long long s; DUP(s, (&a[r].x)[j]);
                    FMA2(acc[r][0], s, w0.x);
                    FMA2(acc[r][1], s, w0.y);
                    if (NCOL == 384) FMA2(acc[r][2], s, w2);
                }
            }
        }
        __syncthreads();
    }

#pragma unroll
    for (int r = 0; r < 8; r++) {
        size_t base = (size_t)(ty * 8 + r) * ldc + colbase;
        float f0, f1, f2, f3;
        UNPK(f0, f1, acc[r][0]); UNPK(f2, f3, acc[r][1]);
        *(float4*)(C + base + tx * 4) = make_float4(f0, f1, f2, f3);
        if (NCOL == 384) {
            float f4, f5; UNPK(f4, f5, acc[r][2]);
            *(float2*)(C + base + 256 + tx * 2) = make_float2(f4, f5);
        }
    }
}

// ---------------------------------------------------------------------------
// ph4: reduce 16 f/i partials + gates + longterm + swish chain + both
// LayerNorms. One CTA (512 threads) per batch row b, 2 elems per thread.
// ---------------------------------------------------------------------------
__device__ __noinline__ void fi_epi(int b,
    const float* __restrict__ g1, const float* __restrict__ b1,
    const float* __restrict__ g2, const float* __restrict__ b2)
{
    __shared__ float red[4][16];
    const int t = threadIdx.x;
    float st[2], lt[2];
    float s1 = 0.f, s2 = 0.f, s3 = 0.f, s4 = 0.f;

#pragma unroll
    for (int i = 0; i < 2; i++) {
        int j = t + i * NT;
        int base = b * 2048 + j;
        float fa = 0.f, ia = 0.f;
#pragma unroll
        for (int sp = 0; sp < 16; sp++) {
            fa += g_fip[sp][base];
            ia += g_fip[sp][base + 1024];
        }
        float xxv = g_xx[b * UU + j];
        float f    = 1.0f / (1.0f + expf(-fa));
        float ii   = 1.0f / (1.0f + expf(-ia));
        float cand = tanhf(xxv);
        float ltv  = f * g_c[b * UU + j] + ii * cand;
        float sxx  = xxv / (1.0f + expf(-xxv));            // swish(xx)
        float z    = ltv + sxx;
        float stv  = z / (1.0f + expf(-z));                // swish(lt + swish(xx))
        st[i] = stv; lt[i] = ltv;
        s1 += stv; s2 += stv * stv; s3 += ltv; s4 += ltv * ltv;
    }

    const int lane = t & 31, wid = t >> 5;
#pragma unroll
    for (int o = 16; o > 0; o >>= 1) {
        s1 += __shfl_down_sync(0xffffffffu, s1, o);
        s2 += __shfl_down_sync(0xffffffffu, s2, o);
        s3 += __shfl_down_sync(0xffffffffu, s3, o);
        s4 += __shfl_down_sync(0xffffffffu, s4, o);
    }
    if (lane == 0) { red[0][wid] = s1; red[1][wid] = s2; red[2][wid] = s3; red[3][wid] = s4; }
    __syncthreads();
    float S1 = 0.f, S2 = 0.f, S3 = 0.f, S4 = 0.f;
#pragma unroll
    for (int w = 0; w < 16; w++) { S1 += red[0][w]; S2 += red[1][w]; S3 += red[2][w]; S4 += red[3][w]; }
    const float inv = 1.0f / (float)UU;
    float m1 = S1 * inv, v1 = S2 * inv - m1 * m1;
    float m2 = S3 * inv, v2 = S4 * inv - m2 * m2;
    float r1 = rsqrtf(v1 + 1e-3f);
    float r2 = rsqrtf(v2 + 1e-3f);

#pragma unroll
    for (int i = 0; i < 2; i++) {
        int j = t + i * NT;
        g_st1[b * UU + j] = (st[i] - m1) * r1 * g1[j] + b1[j];
        g_c[b * UU + j]   = (lt[i] - m2) * r2 * g2[j] + b2[j];
    }
}

// ---------------------------------------------------------------------------
// ph6: mini 8-head attention, one CTA (512 threads) per batch row,
// reduces 16 qkv partials.
// ---------------------------------------------------------------------------
__device__ __noinline__ void attn(int b)
{
    extern __shared__ float dsm[];
    float* q  = dsm;
    float* k  = dsm + 1024;
    float* v  = dsm + 2048;
    float* sc = dsm + 3072;
    const int t = threadIdx.x;

    for (int j = t; j < 3072; j += NT) {
        int base = b * 3072 + j;
        float s = 0.f;
#pragma unroll
        for (int sp = 0; sp < 16; sp++) s += g_qkvp[sp][base];
        if (j < 1024)       q[j] = s;
        else if (j < 2048)  k[j - 1024] = s;
        else                v[j - 2048] = s;
    }
    __syncthreads();

    if (t < 64) {
        int h = t >> 3, g = t & 7;
        float s = 0.f;
#pragma unroll 8
        for (int d = 0; d < 128; d++) s += q[h * 128 + d] * k[g * 128 + d];
        sc[t] = s * 0.08838834764831845f;   // 1/sqrt(128)
    }
    __syncthreads();

    if (t < 8) {
        float mx = -1e30f;
#pragma unroll
        for (int g = 0; g < 8; g++) mx = fmaxf(mx, sc[t * 8 + g]);
        float e[8], sum = 0.f;
#pragma unroll
        for (int g = 0; g < 8; g++) { e[g] = expf(sc[t * 8 + g] - mx); sum += e[g]; }
        float is = 1.0f / sum;
#pragma unroll
        for (int g = 0; g < 8; g++) sc[t * 8 + g] = e[g] * is;
    }
    __syncthreads();

    for (int j = t; j < 1024; j += NT) {
        int h = j >> 7, d = j & 127;
        float a = 0.f;
#pragma unroll
        for (int g = 0; g < 8; g++) a += sc[h * 8 + g] * v[g * 128 + d];
        g_att[b * UU + j] = a;
    }
}

// ---------------------------------------------------------------------------
// The single persistent kernel (phase structure identical to passing R14).
// ---------------------------------------------------------------------------
__global__ void __launch_bounds__(NT, 1) persist(
    const float* __restrict__ x,  const float* __restrict__ kx, const float* __restrict__ kh,
    const float* __restrict__ Wq, const float* __restrict__ Wk, const float* __restrict__ Wv,
    const float* __restrict__ Wo, const float* __restrict__ Wf, const float* __restrict__ Wi,
    const float* __restrict__ g1, const float* __restrict__ b1,
    const float* __restrict__ g2, const float* __restrict__ b2,
    float* __restrict__ y)
{
    unsigned phase = g_release;                 // carries across launches
    const int tid = threadIdx.x;
    const int bid = blockIdx.x;
    const int gt  = bid * NT + tid;             // 0..65535

    // phase 0: pack fused weights, zero carry
    for (int i = gt; i < UU * 2048; i += NB * NT) {
        int kk = i >> 11, j = i & 2047;
        g_Wfi[i] = (j < 1024) ? Wf[(kk << 10) + j] : Wi[(kk << 10) + j - 1024];
    }
    for (int i = gt; i < UU * 3072; i += NB * NT) {
        int kk = i / 3072, j = i - kk * 3072;
        float vv = (j < 1024) ? Wq[kk * 1024 + j]
                 : (j < 2048) ? Wk[kk * 1024 + j - 1024]
                              : Wv[kk * 1024 + j - 2048];
        g_Wqkv[i] = vv;
    }
    g_c[gt] = 0.f;
    gsync(phase);

    // XP = x @ kernel_x : 256 rowtiles x 4 coltiles(256), full K=512
    for (int u = bid; u < 1024; u += NB) {
        int rt = u >> 2, ct = u & 3;
        gemm_tile<256>(x + (size_t)rt * 64 * FF, FF, kx, UU,
                       g_XP + (size_t)rt * 64 * UU, UU, ct * 256, 0, FF);
    }
    gsync(phase);

    for (int t = 0; t < TT; t++) {
        const float* h = (t == 0) ? g_zero : (y + (size_t)(t - 1) * UU);
        const int ldh  = (t == 0) ? UU : (TT * UU);

        // ph1: xx partials = h @ kernel_h  (4 ct(256) x 32 sp, ksz 32)
        {
            int ks = bid >> 2, ct = bid & 3;
            gemm_tile<256>(h, ldh, kh, UU, g_xxp[ks], UU, ct * 256, ks * 32, 32);
        }
        gsync(phase);

        // ph2: xx = XP[:,t,:] + sum of 32 partials (exactly 1 elem/thread)
        {
            int b = gt >> 10, uu = gt & 1023;
            float s = g_XP[(size_t)((b << 8) + t) * UU + uu];
#pragma unroll
            for (int sp = 0; sp < 32; sp++) s += g_xxp[sp][gt];
            g_xx[gt] = s;
        }
        gsync(phase);

        // ph3: [f|i] partials = xx @ Wfi  (8 ct(256) x 16 sp, ksz 64)
        {
            int ks = bid >> 3, ct = bid & 7;
            gemm_tile<256>(g_xx, UU, g_Wfi, 2048, g_fip[ks], 2048,
                           ct * 256, ks * 64, 64);
        }
        gsync(phase);

        // ph4: gates + swish + both LayerNorms
        if (bid < 64) fi_epi(bid, g1, b1, g2, b2);
        gsync(phase);

        // ph5: [q|k|v] partials = st1 @ Wqkv  (8 ct(384) x 16 sp, ksz 64)
        {
            int ks = bid >> 3, ct = bid & 7;
            gemm_tile<384>(g_st1, UU, g_Wqkv, 3072, g_qkvp[ks], 3072,
                           ct * 384, ks * 64, 64);
        }
        gsync(phase);

        // ph6: attention
        if (bid < 64) attn(bid);
        gsync(phase);

        // ph7: out partials = attended @ W_o  (4 ct(256) x 32 sp, ksz 32)
        {
            int ks = bid >> 2, ct = bid & 3;
            gemm_tile<256>(g_att, UU, Wo, UU, g_outp[ks], UU, ct * 256, ks * 32, 32);
        }
        gsync(phase);

        // ph8: y[:,t,:] = st1 + sum of 32 partials  (= h for t+1)
        {
            int b = gt >> 10, uu = gt & 1023;
            float s = g_st1[gt];
#pragma unroll
            for (int sp = 0; sp < 32; sp++) s += g_outp[sp][gt];
            y[(size_t)b * (TT * UU) + (size_t)t * UU + uu] = s;
        }
        gsync(phase);
    }
}

// ---------------------------------------------------------------------------
// Host: ONE launch -> one graph node.
// ---------------------------------------------------------------------------
extern "C" void kernel_launch(void* const* d_in, const int* in_sizes, int n_in,
                              void* d_out, int out_size)
{
    (void)in_sizes; (void)n_in; (void)out_size;
    cudaFuncSetAttribute(persist, cudaFuncAttributeMaxDynamicSharedMemorySize,
                         SMEM_BYTES);
    persist<<<NB, NT, SMEM_BYTES>>>(
        (const float*)d_in[0],  (const float*)d_in[1],  (const float*)d_in[2],
        (const float*)d_in[3],  (const float*)d_in[4],  (const float*)d_in[5],
        (const float*)d_in[6],  (const float*)d_in[7],  (const float*)d_in[8],
        (const float*)d_in[9],  (const float*)d_in[10],
        (const float*)d_in[11], (const float*)d_in[12],
        (float*)d_out);
}